// round 5
// baseline (speedup 1.0000x reference)
#include <cuda_runtime.h>
#include <cuda_bf16.h>
#include <cstdint>

#define EMBED 1024
#define HEADS 16
#define HD 64
#define NBATCH 2
#define SEQ 2048
#define MROWS (NBATCH * SEQ)   // 4096

// ---------------- scratch (allocation-free: __device__ globals) ----------------
__device__ float g_Q[(size_t)NBATCH * HEADS * SEQ * HD];   // [b,h,l,d]
__device__ float g_K[(size_t)NBATCH * HEADS * SEQ * HD];
__device__ float g_V[(size_t)NBATCH * HEADS * SEQ * HD];
__device__ float g_O[(size_t)MROWS * EMBED];               // [b*l, e] pre-Wo

// ---------------- tiled SGEMM body: C(128x128) = A(128xK) * B(128xK)^T --------
// A, B already offset to the block tile. 256 threads, 8x8 per thread,
// split 4+4 register tiling for conflict-free float4 smem reads.
__device__ __forceinline__ void gemm_tile_abt(const float* __restrict__ A,
                                              const float* __restrict__ B,
                                              int K, float acc[8][8]) {
    __shared__ float As[8][128];
    __shared__ float Bs[8][128];

    const int tid = threadIdx.x;
    const int lr  = tid >> 1;          // row within tile (0..127)
    const int lk  = (tid & 1) << 2;    // 0 or 4
    const int ty  = tid >> 4;          // 0..15
    const int tx  = tid & 15;          // 0..15

    const float* Ap = A + (size_t)lr * K + lk;
    const float* Bp = B + (size_t)lr * K + lk;

    for (int k0 = 0; k0 < K; k0 += 8) {
        float4 av = *(const float4*)(Ap + k0);
        float4 bv = *(const float4*)(Bp + k0);
        __syncthreads();
        As[lk + 0][lr] = av.x; As[lk + 1][lr] = av.y;
        As[lk + 2][lr] = av.z; As[lk + 3][lr] = av.w;
        Bs[lk + 0][lr] = bv.x; Bs[lk + 1][lr] = bv.y;
        Bs[lk + 2][lr] = bv.z; Bs[lk + 3][lr] = bv.w;
        __syncthreads();

#pragma unroll
        for (int k = 0; k < 8; k++) {
            float a[8], b[8];
            *(float4*)(a)     = *(const float4*)&As[k][ty * 4];
            *(float4*)(a + 4) = *(const float4*)&As[k][64 + ty * 4];
            *(float4*)(b)     = *(const float4*)&Bs[k][tx * 4];
            *(float4*)(b + 4) = *(const float4*)&Bs[k][64 + tx * 4];
#pragma unroll
            for (int i = 0; i < 8; i++)
#pragma unroll
                for (int j = 0; j < 8; j++)
                    acc[i][j] += a[i] * b[j];
        }
    }
}

// ---------------- QKV projection (one launch, z selects q/k/v) ----------------
// out[row, col] = sum_k in[row,k] * W[col,k]; scattered to head-major [b,h,l,d]
__global__ void __launch_bounds__(256) qkv_kernel(
    const float* __restrict__ q_in, const float* __restrict__ k_in,
    const float* __restrict__ v_in, const float* __restrict__ Wq,
    const float* __restrict__ Wk, const float* __restrict__ Wv) {
    const int z = blockIdx.z;
    const float* A = (z == 0) ? q_in : (z == 1) ? k_in : v_in;
    const float* W = (z == 0) ? Wq : (z == 1) ? Wk : Wv;
    float* dst = (z == 0) ? g_Q : (z == 1) ? g_K : g_V;

    A += (size_t)blockIdx.y * 128 * EMBED;
    W += (size_t)blockIdx.x * 128 * EMBED;

    float acc[8][8] = {};
    gemm_tile_abt(A, W, EMBED, acc);

    const int ty = threadIdx.x >> 4, tx = threadIdx.x & 15;
#pragma unroll
    for (int i = 0; i < 8; i++) {
        const int r = blockIdx.y * 128 + ((i < 4) ? ty * 4 + i : 64 + ty * 4 + i - 4);
        const int b = r >> 11;      // / SEQ
        const int l = r & (SEQ - 1);
#pragma unroll
        for (int j = 0; j < 8; j++) {
            const int c = blockIdx.x * 128 + ((j < 4) ? tx * 4 + j : 64 + tx * 4 + j - 4);
            const int h = c >> 6;
            const int d = c & 63;
            dst[(((size_t)(b * HEADS + h)) * SEQ + l) * HD + d] = acc[i][j];
        }
    }
}

// ---------------- output projection: out = g_O @ Wo^T + bo --------------------
__global__ void __launch_bounds__(256) oproj_kernel(const float* __restrict__ Wo,
                                                    const float* __restrict__ bo,
                                                    float* __restrict__ out) {
    const float* A = g_O + (size_t)blockIdx.y * 128 * EMBED;
    const float* W = Wo  + (size_t)blockIdx.x * 128 * EMBED;

    float acc[8][8] = {};
    gemm_tile_abt(A, W, EMBED, acc);

    const int ty = threadIdx.x >> 4, tx = threadIdx.x & 15;
#pragma unroll
    for (int i = 0; i < 8; i++) {
        const int r = blockIdx.y * 128 + ((i < 4) ? ty * 4 + i : 64 + ty * 4 + i - 4);
#pragma unroll
        for (int j = 0; j < 8; j++) {
            const int c = blockIdx.x * 128 + ((j < 4) ? tx * 4 + j : 64 + tx * 4 + j - 4);
            out[(size_t)r * EMBED + c] = acc[i][j] + __ldg(&bo[c]);
        }
    }
}

// ---------------- flash attention (fp32, online softmax) ---------------------
// Block = (b, h, 64-query tile). K-tiles of 64. 256 threads = 16x16,
// each thread owns a 4x4 tile. Q/K/P stored transposed in smem so both
// inner products are float4-vectorized (2x LDS.128 + 16 FFMA per k-step).
#define BQ 64
#define BKT 64
#define PAD 68   // 64 + 4: kills bank conflicts, keeps 16B alignment

__global__ void __launch_bounds__(256) attn_kernel(const int* __restrict__ mask) {
    extern __shared__ float sm[];
    float* Qts = sm;                 // [HD][PAD]  Qts[d*PAD + r]  (transposed)
    float* Kts = sm + 64 * PAD;      // [HD][PAD]  Kts[d*PAD + c]  (transposed)
    float* Vs  = sm + 2 * 64 * PAD;  // [BKT][PAD] Vs[kc*PAD + d]
    float* Pt  = sm + 3 * 64 * PAD;  // [BKT][PAD] Pt[kc*PAD + r]  (transposed)

    const int qt = blockIdx.x, h = blockIdx.y, b = blockIdx.z;
    const int tid = threadIdx.x;
    const int ty = tid >> 4, tx = tid & 15;

    const float* Qg = g_Q + ((size_t)(b * HEADS + h) * SEQ + qt * BQ) * HD;
    const float* Kg = g_K + (size_t)(b * HEADS + h) * SEQ * HD;
    const float* Vg = g_V + (size_t)(b * HEADS + h) * SEQ * HD;
    const int*   mp = mask + (size_t)b * SEQ;

    // Load Q tile transposed: Qts[d][r]
    for (int i = tid; i < BQ * 16; i += 256) {
        const int r = i >> 4, c4 = (i & 15) << 2;
        float4 v = *(const float4*)(Qg + r * HD + c4);
        Qts[(c4 + 0) * PAD + r] = v.x;
        Qts[(c4 + 1) * PAD + r] = v.y;
        Qts[(c4 + 2) * PAD + r] = v.z;
        Qts[(c4 + 3) * PAD + r] = v.w;
    }

    float acc[4][4] = {};
    float m_i[4], l_i[4];
#pragma unroll
    for (int i = 0; i < 4; i++) { m_i[i] = -3.0e38f; l_i[i] = 0.f; }

    for (int kt = 0; kt < SEQ / BKT; kt++) {
        __syncthreads();  // previous PV reads of Pt/Vs done before overwrite
        // Load K transposed + V
        for (int i = tid; i < BKT * 16; i += 256) {
            const int r = i >> 4, c4 = (i & 15) << 2;
            float4 kv = *(const float4*)(Kg + (size_t)(kt * BKT + r) * HD + c4);
            Kts[(c4 + 0) * PAD + r] = kv.x;
            Kts[(c4 + 1) * PAD + r] = kv.y;
            Kts[(c4 + 2) * PAD + r] = kv.z;
            Kts[(c4 + 3) * PAD + r] = kv.w;
            float4 vv = *(const float4*)(Vg + (size_t)(kt * BKT + r) * HD + c4);
            *(float4*)(Vs + r * PAD + c4) = vv;
        }
        __syncthreads();

        // S = Q * K^T for this tile (4x4 per thread, rows ty*4+i, cols tx*4+j)
        float s[4][4] = {};
#pragma unroll 8
        for (int k = 0; k < HD; k++) {
            float4 aq = *(const float4*)(Qts + k * PAD + ty * 4);
            float4 bk = *(const float4*)(Kts + k * PAD + tx * 4);
            const float av[4] = {aq.x, aq.y, aq.z, aq.w};
            const float bv[4] = {bk.x, bk.y, bk.z, bk.w};
#pragma unroll
            for (int i = 0; i < 4; i++)
#pragma unroll
                for (int j = 0; j < 4; j++)
                    s[i][j] += av[i] * bv[j];
        }

        // scale + mask (mask broadcast over heads/queries; per key position)
        const float scale = 0.125f;  // 1/sqrt(HD)
        int mv[4];
#pragma unroll
        for (int j = 0; j < 4; j++) mv[j] = __ldg(&mp[kt * BKT + tx * 4 + j]);

        float sc_old[4];
#pragma unroll
        for (int i = 0; i < 4; i++) {
            float rmax = -3.0e38f;
#pragma unroll
            for (int j = 0; j < 4; j++) {
                s[i][j] = mv[j] ? s[i][j] * scale : -1.0e20f;
                rmax = fmaxf(rmax, s[i][j]);
            }
#pragma unroll
            for (int off = 8; off > 0; off >>= 1)
                rmax = fmaxf(rmax, __shfl_xor_sync(0xffffffffu, rmax, off, 16));

            const float mn = fmaxf(m_i[i], rmax);
            sc_old[i] = __expf(m_i[i] - mn);
            m_i[i] = mn;

            float rsum = 0.f;
#pragma unroll
            for (int j = 0; j < 4; j++) {
                s[i][j] = __expf(s[i][j] - mn);
                rsum += s[i][j];
            }
#pragma unroll
            for (int off = 8; off > 0; off >>= 1)
                rsum += __shfl_xor_sync(0xffffffffu, rsum, off, 16);
            l_i[i] = l_i[i] * sc_old[i] + rsum;
        }

        // Store P transposed: Pt[kc][r]
#pragma unroll
        for (int j = 0; j < 4; j++) {
            float4 pv = make_float4(s[0][j], s[1][j], s[2][j], s[3][j]);
            *(float4*)(Pt + (tx * 4 + j) * PAD + ty * 4) = pv;
        }
#pragma unroll
        for (int i = 0; i < 4; i++)
#pragma unroll
            for (int j = 0; j < 4; j++)
                acc[i][j] *= sc_old[i];

        __syncthreads();  // all P written

        // acc += P * V  (thread cols j -> d = tx*4+j)
#pragma unroll 8
        for (int k = 0; k < BKT; k++) {
            float4 pq = *(const float4*)(Pt + k * PAD + ty * 4);
            float4 vq = *(const float4*)(Vs + k * PAD + tx * 4);
            const float pv[4] = {pq.x, pq.y, pq.z, pq.w};
            const float vv[4] = {vq.x, vq.y, vq.z, vq.w};
#pragma unroll
            for (int i = 0; i < 4; i++)
#pragma unroll
                for (int j = 0; j < 4; j++)
                    acc[i][j] += pv[i] * vv[j];
        }
    }

    // epilogue: normalize, store to g_O in [b*l, e] row-major
#pragma unroll
    for (int i = 0; i < 4; i++) {
        const float inv = 1.0f / l_i[i];
        const int r = qt * BQ + ty * 4 + i;
#pragma unroll
        for (int j = 0; j < 4; j++) {
            const int d = tx * 4 + j;
            g_O[((size_t)b * SEQ + r) * EMBED + h * HD + d] = acc[i][j] * inv;
        }
    }
}

// ---------------- launcher ---------------------------------------------------
extern "C" void kernel_launch(void* const* d_in, const int* in_sizes, int n_in,
                              void* d_out, int out_size) {
    const float* values = (const float*)d_in[0];
    const float* keys   = (const float*)d_in[1];
    const float* query  = (const float*)d_in[2];
    const int*   mask   = (const int*)d_in[3];
    const float* Wq     = (const float*)d_in[4];
    const float* Wk     = (const float*)d_in[5];
    const float* Wv     = (const float*)d_in[6];
    const float* Wo     = (const float*)d_in[7];
    const float* bo     = (const float*)d_in[8];
    float* out = (float*)d_out;

    // 4 arrays of [64][68] floats = 69632 B dynamic smem for attention.
    // Attribute is persistent per-function; first (non-capture) correctness
    // call establishes it, so capture-time repeats are harmless.
    const int attn_smem = 4 * 64 * PAD * (int)sizeof(float);
    cudaFuncSetAttribute(attn_kernel, cudaFuncAttributeMaxDynamicSharedMemorySize,
                         attn_smem);

    // Q/K/V projections: 3 GEMMs of 4096x1024x1024
    dim3 gproj(EMBED / 128, MROWS / 128, 3);
    qkv_kernel<<<gproj, 256>>>(query, keys, values, Wq, Wk, Wv);

    // Flash attention: (32 q-tiles, 16 heads, 2 batches)
    dim3 gattn(SEQ / BQ, HEADS, NBATCH);
    attn_kernel<<<gattn, 256, attn_smem>>>(mask);

    // Output projection + bias
    dim3 gout(EMBED / 128, MROWS / 128);
    oproj_kernel<<<gout, 256>>>(Wo, bo, out);
}

// round 10
// speedup vs baseline: 2.3987x; 2.3987x over previous
#include <cuda_runtime.h>
#include <cstdint>

#define EMBED 1024
#define HEADS 16
#define HD 64
#define NBATCH 2
#define SEQ 2048
#define MROWS (NBATCH * SEQ)   // 4096

// ---------------- scratch (allocation-free: __device__ globals) --------------
__device__ float g_Q[(size_t)NBATCH * HEADS * SEQ * HD];   // [b,h,l,d]
__device__ float g_K[(size_t)NBATCH * HEADS * SEQ * HD];
__device__ float g_V[(size_t)NBATCH * HEADS * SEQ * HD];
__device__ float g_O[(size_t)MROWS * EMBED];               // [b*l, e] pre-Wo

// ---------------- tf32 helpers ----------------------------------------------
__device__ __forceinline__ unsigned f2tf(float f) {
    unsigned u;
    asm("cvt.rna.tf32.f32 %0, %1;" : "=r"(u) : "f"(f));
    return u;
}

// D += A(16x8, row) * B(8x8, col), tf32 in, fp32 accum
__device__ __forceinline__ void mma8(float* c, unsigned a0, unsigned a1,
                                     unsigned a2, unsigned a3,
                                     unsigned b0, unsigned b1) {
    asm volatile(
        "mma.sync.aligned.m16n8k8.row.col.f32.tf32.tf32.f32 "
        "{%0,%1,%2,%3}, {%4,%5,%6,%7}, {%8,%9}, {%0,%1,%2,%3};"
        : "+f"(c[0]), "+f"(c[1]), "+f"(c[2]), "+f"(c[3])
        : "r"(a0), "r"(a1), "r"(a2), "r"(a3), "r"(b0), "r"(b1));
}

// =============================================================================
// Projection GEMM: C(128x128) = A(128xK) * B(128xK)^T, tf32 mma, K-step 16.
// 8 warps: warp = 32 rows x 64 cols (2 m-tiles x 8 n-tiles of m16n8).
// smem stride 136 (== 8 mod 32) -> all fragment LDS conflict-free.
// =============================================================================
#define GSTR 136

__device__ __forceinline__ void gemm_mma_abt(const float* __restrict__ A,
                                             const float* __restrict__ B,
                                             float acc[2][8][4]) {
    __shared__ unsigned As[16][GSTR];
    __shared__ unsigned Bs[16][GSTR];

    const int tid  = threadIdx.x;
    const int lane = tid & 31, wid = tid >> 5;
    const int wm = wid >> 1, wn = wid & 1;        // 4 x 2 warp grid
    const int g  = lane >> 2, t4 = lane & 3;
    const int lr = tid >> 1;                      // 0..127
    const int lk = (tid & 1) * 8;                 // 0 or 8

    const float* Ap = A + (size_t)lr * EMBED + lk;
    const float* Bp = B + (size_t)lr * EMBED + lk;

    for (int k0 = 0; k0 < EMBED; k0 += 16) {
        float4 av0 = *(const float4*)(Ap + k0);
        float4 av1 = *(const float4*)(Ap + k0 + 4);
        float4 bv0 = *(const float4*)(Bp + k0);
        float4 bv1 = *(const float4*)(Bp + k0 + 4);
        __syncthreads();
        As[lk + 0][lr] = f2tf(av0.x); As[lk + 1][lr] = f2tf(av0.y);
        As[lk + 2][lr] = f2tf(av0.z); As[lk + 3][lr] = f2tf(av0.w);
        As[lk + 4][lr] = f2tf(av1.x); As[lk + 5][lr] = f2tf(av1.y);
        As[lk + 6][lr] = f2tf(av1.z); As[lk + 7][lr] = f2tf(av1.w);
        Bs[lk + 0][lr] = f2tf(bv0.x); Bs[lk + 1][lr] = f2tf(bv0.y);
        Bs[lk + 2][lr] = f2tf(bv0.z); Bs[lk + 3][lr] = f2tf(bv0.w);
        Bs[lk + 4][lr] = f2tf(bv1.x); Bs[lk + 5][lr] = f2tf(bv1.y);
        Bs[lk + 6][lr] = f2tf(bv1.z); Bs[lk + 7][lr] = f2tf(bv1.w);
        __syncthreads();

#pragma unroll
        for (int kk = 0; kk < 16; kk += 8) {
            unsigned af[2][4];
#pragma unroll
            for (int mt = 0; mt < 2; mt++) {
                const int r0 = wm * 32 + mt * 16 + g;
                af[mt][0] = As[kk + t4][r0];
                af[mt][1] = As[kk + t4][r0 + 8];
                af[mt][2] = As[kk + t4 + 4][r0];
                af[mt][3] = As[kk + t4 + 4][r0 + 8];
            }
            unsigned bf[8][2];
#pragma unroll
            for (int nt = 0; nt < 8; nt++) {
                const int cb = wn * 64 + nt * 8 + g;
                bf[nt][0] = Bs[kk + t4][cb];
                bf[nt][1] = Bs[kk + t4 + 4][cb];
            }
#pragma unroll
            for (int mt = 0; mt < 2; mt++)
#pragma unroll
                for (int nt = 0; nt < 8; nt++)
                    mma8(acc[mt][nt], af[mt][0], af[mt][1], af[mt][2], af[mt][3],
                         bf[nt][0], bf[nt][1]);
        }
    }
}

// QKV projection, scattered to head-major [b,h,l,d]
__global__ void __launch_bounds__(256) qkv_kernel(
    const float* __restrict__ q_in, const float* __restrict__ k_in,
    const float* __restrict__ v_in, const float* __restrict__ Wq,
    const float* __restrict__ Wk, const float* __restrict__ Wv) {
    const int z = blockIdx.z;
    const float* A = (z == 0) ? q_in : (z == 1) ? k_in : v_in;
    const float* W = (z == 0) ? Wq : (z == 1) ? Wk : Wv;
    float* dst = (z == 0) ? g_Q : (z == 1) ? g_K : g_V;

    A += (size_t)blockIdx.y * 128 * EMBED;
    W += (size_t)blockIdx.x * 128 * EMBED;

    float acc[2][8][4] = {};
    gemm_mma_abt(A, W, acc);

    const int lane = threadIdx.x & 31, wid = threadIdx.x >> 5;
    const int wm = wid >> 1, wn = wid & 1;
    const int g = lane >> 2, t4 = lane & 3;

#pragma unroll
    for (int mt = 0; mt < 2; mt++) {
#pragma unroll
        for (int rh = 0; rh < 2; rh++) {
            const int r = blockIdx.y * 128 + wm * 32 + mt * 16 + g + rh * 8;
            const int b = r >> 11, l = r & (SEQ - 1);
#pragma unroll
            for (int nt = 0; nt < 8; nt++) {
                const int c = blockIdx.x * 128 + wn * 64 + nt * 8 + t4 * 2;
                const int h = c >> 6, d = c & 63;
                float2 v = make_float2(acc[mt][nt][rh * 2], acc[mt][nt][rh * 2 + 1]);
                *(float2*)&dst[(((size_t)(b * HEADS + h)) * SEQ + l) * HD + d] = v;
            }
        }
    }
}

// Output projection: out = g_O @ Wo^T + bo
__global__ void __launch_bounds__(256) oproj_kernel(const float* __restrict__ Wo,
                                                    const float* __restrict__ bo,
                                                    float* __restrict__ out) {
    const float* A = g_O + (size_t)blockIdx.y * 128 * EMBED;
    const float* W = Wo  + (size_t)blockIdx.x * 128 * EMBED;

    float acc[2][8][4] = {};
    gemm_mma_abt(A, W, acc);

    const int lane = threadIdx.x & 31, wid = threadIdx.x >> 5;
    const int wm = wid >> 1, wn = wid & 1;
    const int g = lane >> 2, t4 = lane & 3;

#pragma unroll
    for (int mt = 0; mt < 2; mt++) {
#pragma unroll
        for (int rh = 0; rh < 2; rh++) {
            const int r = blockIdx.y * 128 + wm * 32 + mt * 16 + g + rh * 8;
#pragma unroll
            for (int nt = 0; nt < 8; nt++) {
                const int c = blockIdx.x * 128 + wn * 64 + nt * 8 + t4 * 2;
                float2 bb = *(const float2*)&bo[c];
                float2 v = make_float2(acc[mt][nt][rh * 2] + bb.x,
                                       acc[mt][nt][rh * 2 + 1] + bb.y);
                *(float2*)&out[(size_t)r * EMBED + c] = v;
            }
        }
    }
}

// =============================================================================
// Flash attention, tf32 mma. Q-tile 128, K-tile 64, Dh=64.
// 8 warps: 4x2 (32 rows x 32 cols each) for both S=QK^T and O=PV.
// =============================================================================
#define AQ 128
#define AK 64
#define QSTR 136   // stride for 128-wide transposed tiles (== 8 mod 32)
#define KSTR 72    // stride for  64-wide tiles            (== 8 mod 32)

__global__ void __launch_bounds__(256) attn_kernel(const int* __restrict__ mask) {
    extern __shared__ unsigned smu[];
    unsigned* Qts = smu;                       // [64][QSTR] tf32, Qts[d][row]
    unsigned* Kts = Qts + 64 * QSTR;           // [64][KSTR] tf32, Kts[d][key]
    unsigned* Vs  = Kts + 64 * KSTR;           // [64][KSTR] tf32, Vs[key][d]
    unsigned* Pt  = Vs  + 64 * KSTR;           // [64][QSTR] tf32, Pt[key][row]
    float*    red = (float*)(Pt + 64 * QSTR);  // [4][128]: [0..1]=max, [2..3]=sum

    const int qt = blockIdx.x, h = blockIdx.y, b = blockIdx.z;
    const int tid = threadIdx.x, lane = tid & 31, wid = tid >> 5;
    const int wm = wid >> 1, wn = wid & 1;
    const int g = lane >> 2, t4 = lane & 3;

    const float* Qg = g_Q + ((size_t)(b * HEADS + h) * SEQ + qt * AQ) * HD;
    const float* Kg = g_K + (size_t)(b * HEADS + h) * SEQ * HD;
    const float* Vg = g_V + (size_t)(b * HEADS + h) * SEQ * HD;
    const int*   mp = mask + (size_t)b * SEQ;

    // Load Q transposed (row-distinct mapping -> conflict-free STS)
    for (int i = tid; i < 128 * 16; i += 256) {
        const int r = i & 127, c4 = (i >> 7) << 2;
        float4 q = *(const float4*)(Qg + (size_t)r * HD + c4);
        Qts[(c4 + 0) * QSTR + r] = f2tf(q.x);
        Qts[(c4 + 1) * QSTR + r] = f2tf(q.y);
        Qts[(c4 + 2) * QSTR + r] = f2tf(q.z);
        Qts[(c4 + 3) * QSTR + r] = f2tf(q.w);
    }

    float accO[2][4][4] = {};
    float m_i[2][2], l_i[2][2];
#pragma unroll
    for (int a = 0; a < 2; a++)
#pragma unroll
        for (int c = 0; c < 2; c++) { m_i[a][c] = -3.0e38f; l_i[a][c] = 0.f; }

    for (int kt = 0; kt < SEQ / AK; kt++) {
        __syncthreads();   // prev-iter readers of Kts/Vs done
        // K transposed (row-distinct i-mapping: conflict-free STS, L2 absorbs gmem)
        for (int i = tid; i < 64 * 16; i += 256) {
            const int r = i & 63, c4 = (i >> 6) << 2;
            float4 kq = *(const float4*)(Kg + (size_t)(kt * AK + r) * HD + c4);
            Kts[(c4 + 0) * KSTR + r] = f2tf(kq.x);
            Kts[(c4 + 1) * KSTR + r] = f2tf(kq.y);
            Kts[(c4 + 2) * KSTR + r] = f2tf(kq.z);
            Kts[(c4 + 3) * KSTR + r] = f2tf(kq.w);
        }
        // V natural layout (col-major i-mapping: coalesced gmem, uint4 STS)
        for (int i = tid; i < 64 * 16; i += 256) {
            const int r = i >> 4, c4 = (i & 15) << 2;
            float4 vq = *(const float4*)(Vg + (size_t)(kt * AK + r) * HD + c4);
            uint4 u = make_uint4(f2tf(vq.x), f2tf(vq.y), f2tf(vq.z), f2tf(vq.w));
            *(uint4*)(Vs + r * KSTR + c4) = u;
        }
        __syncthreads();

        // ---- S = Q * K^T (warp: 32 rows x 32 cols) ----
        float s[2][4][4] = {};
#pragma unroll
        for (int k8 = 0; k8 < 64; k8 += 8) {
            unsigned af[2][4];
#pragma unroll
            for (int mt = 0; mt < 2; mt++) {
                const int r0 = wm * 32 + mt * 16 + g;
                af[mt][0] = Qts[(k8 + t4) * QSTR + r0];
                af[mt][1] = Qts[(k8 + t4) * QSTR + r0 + 8];
                af[mt][2] = Qts[(k8 + t4 + 4) * QSTR + r0];
                af[mt][3] = Qts[(k8 + t4 + 4) * QSTR + r0 + 8];
            }
            unsigned bf[4][2];
#pragma unroll
            for (int nt = 0; nt < 4; nt++) {
                const int cb = wn * 32 + nt * 8 + g;
                bf[nt][0] = Kts[(k8 + t4) * KSTR + cb];
                bf[nt][1] = Kts[(k8 + t4 + 4) * KSTR + cb];
            }
#pragma unroll
            for (int mt = 0; mt < 2; mt++)
#pragma unroll
                for (int nt = 0; nt < 4; nt++)
                    mma8(s[mt][nt], af[mt][0], af[mt][1], af[mt][2], af[mt][3],
                         bf[nt][0], bf[nt][1]);
        }

        // ---- mask + scale ----
        const float scale = 0.125f;   // 1/sqrt(64)
        int mv[4][2];
#pragma unroll
        for (int nt = 0; nt < 4; nt++) {
#pragma unroll
            for (int e = 0; e < 2; e++)
                mv[nt][e] = __ldg(&mp[kt * AK + wn * 32 + nt * 8 + t4 * 2 + e]);
        }
#pragma unroll
        for (int mt = 0; mt < 2; mt++)
#pragma unroll
            for (int nt = 0; nt < 4; nt++)
#pragma unroll
                for (int c = 0; c < 4; c++)
                    s[mt][nt][c] = mv[nt][c & 1] ? s[mt][nt][c] * scale : -1.0e20f;

        // ---- online softmax ----
        float scf[2][2];
        // phase 1: row maxima
#pragma unroll
        for (int mt = 0; mt < 2; mt++) {
#pragma unroll
            for (int rh = 0; rh < 2; rh++) {
                float rm = -3.0e38f;
#pragma unroll
                for (int nt = 0; nt < 4; nt++) {
                    rm = fmaxf(rm, s[mt][nt][rh * 2]);
                    rm = fmaxf(rm, s[mt][nt][rh * 2 + 1]);
                }
                rm = fmaxf(rm, __shfl_xor_sync(0xffffffffu, rm, 1));
                rm = fmaxf(rm, __shfl_xor_sync(0xffffffffu, rm, 2));
                if (t4 == 0) {
                    const int row = wm * 32 + mt * 16 + g + rh * 8;
                    red[wn * 128 + row] = rm;
                }
            }
        }
        __syncthreads();
        // phase 2: exp + partial sums
#pragma unroll
        for (int mt = 0; mt < 2; mt++) {
#pragma unroll
            for (int rh = 0; rh < 2; rh++) {
                const int row = wm * 32 + mt * 16 + g + rh * 8;
                const float rm = fmaxf(red[row], red[128 + row]);
                const float mn = fmaxf(m_i[mt][rh], rm);
                scf[mt][rh] = __expf(m_i[mt][rh] - mn);
                m_i[mt][rh] = mn;
                float ps = 0.f;
#pragma unroll
                for (int nt = 0; nt < 4; nt++) {
                    float e0 = __expf(s[mt][nt][rh * 2] - mn);
                    float e1 = __expf(s[mt][nt][rh * 2 + 1] - mn);
                    s[mt][nt][rh * 2] = e0; s[mt][nt][rh * 2 + 1] = e1;
                    ps += e0 + e1;
                }
                ps += __shfl_xor_sync(0xffffffffu, ps, 1);
                ps += __shfl_xor_sync(0xffffffffu, ps, 2);
                if (t4 == 0) red[(2 + wn) * 128 + row] = ps;
            }
        }
        __syncthreads();
#pragma unroll
        for (int mt = 0; mt < 2; mt++)
#pragma unroll
            for (int rh = 0; rh < 2; rh++) {
                const int row = wm * 32 + mt * 16 + g + rh * 8;
                l_i[mt][rh] = l_i[mt][rh] * scf[mt][rh] + red[256 + row] + red[384 + row];
            }

        // rescale O accumulators
#pragma unroll
        for (int mt = 0; mt < 2; mt++)
#pragma unroll
            for (int nt = 0; nt < 4; nt++)
#pragma unroll
                for (int c = 0; c < 4; c++)
                    accO[mt][nt][c] *= scf[mt][c >> 1];

        // ---- store P transposed (tf32) for PV ----
#pragma unroll
        for (int mt = 0; mt < 2; mt++)
#pragma unroll
            for (int nt = 0; nt < 4; nt++)
#pragma unroll
                for (int c = 0; c < 4; c++) {
                    const int row = wm * 32 + mt * 16 + g + (c >> 1) * 8;
                    const int key = wn * 32 + nt * 8 + t4 * 2 + (c & 1);
                    Pt[key * QSTR + row] = f2tf(s[mt][nt][c]);
                }
        __syncthreads();

        // ---- O += P * V ----
#pragma unroll
        for (int k8 = 0; k8 < 64; k8 += 8) {
            unsigned af[2][4];
#pragma unroll
            for (int mt = 0; mt < 2; mt++) {
                const int r0 = wm * 32 + mt * 16 + g;
                af[mt][0] = Pt[(k8 + t4) * QSTR + r0];
                af[mt][1] = Pt[(k8 + t4) * QSTR + r0 + 8];
                af[mt][2] = Pt[(k8 + t4 + 4) * QSTR + r0];
                af[mt][3] = Pt[(k8 + t4 + 4) * QSTR + r0 + 8];
            }
            unsigned bf[4][2];
#pragma unroll
            for (int nt = 0; nt < 4; nt++) {
                const int cb = wn * 32 + nt * 8 + g;
                bf[nt][0] = Vs[(k8 + t4) * KSTR + cb];
                bf[nt][1] = Vs[(k8 + t4 + 4) * KSTR + cb];
            }
#pragma unroll
            for (int mt = 0; mt < 2; mt++)
#pragma unroll
                for (int nt = 0; nt < 4; nt++)
                    mma8(accO[mt][nt], af[mt][0], af[mt][1], af[mt][2], af[mt][3],
                         bf[nt][0], bf[nt][1]);
        }
    }

    // ---- epilogue: normalize, write g_O [b*l, e] ----
#pragma unroll
    for (int mt = 0; mt < 2; mt++) {
#pragma unroll
        for (int rh = 0; rh < 2; rh++) {
            const float inv = 1.0f / l_i[mt][rh];
            const int row = qt * AQ + wm * 32 + mt * 16 + g + rh * 8;
#pragma unroll
            for (int nt = 0; nt < 4; nt++) {
                const int d = wn * 32 + nt * 8 + t4 * 2;
                float2 v = make_float2(accO[mt][nt][rh * 2] * inv,
                                       accO[mt][nt][rh * 2 + 1] * inv);
                *(float2*)&g_O[((size_t)b * SEQ + row) * EMBED + h * HD + d] = v;
            }
        }
    }
}

// ---------------- launcher ---------------------------------------------------
extern "C" void kernel_launch(void* const* d_in, const int* in_sizes, int n_in,
                              void* d_out, int out_size) {
    const float* values = (const float*)d_in[0];
    const float* keys   = (const float*)d_in[1];
    const float* query  = (const float*)d_in[2];
    const int*   mask   = (const int*)d_in[3];
    const float* Wq     = (const float*)d_in[4];
    const float* Wk     = (const float*)d_in[5];
    const float* Wv     = (const float*)d_in[6];
    const float* Wo     = (const float*)d_in[7];
    const float* bo     = (const float*)d_in[8];
    float* out = (float*)d_out;

    const int attn_smem =
        (64 * QSTR + 64 * KSTR + 64 * KSTR + 64 * QSTR) * (int)sizeof(unsigned)
        + 4 * 128 * (int)sizeof(float);   // ~108.5 KB
    cudaFuncSetAttribute(attn_kernel, cudaFuncAttributeMaxDynamicSharedMemorySize,
                         attn_smem);

    dim3 gproj(EMBED / 128, MROWS / 128, 3);
    qkv_kernel<<<gproj, 256>>>(query, keys, values, Wq, Wk, Wv);

    dim3 gattn(SEQ / AQ, HEADS, NBATCH);
    attn_kernel<<<gattn, 256, attn_smem>>>(mask);

    dim3 gout(EMBED / 128, MROWS / 128);
    oproj_kernel<<<gout, 256>>>(Wo, bo, out);
}

// round 13
// speedup vs baseline: 2.7998x; 1.1672x over previous
#include <cuda_runtime.h>
#include <cstdint>

#define EMBED 1024
#define HEADS 16
#define HD 64
#define NBATCH 2
#define SEQ 2048
#define MROWS (NBATCH * SEQ)   // 4096

// ---------------- scratch (allocation-free: __device__ globals) --------------
__device__ float g_Q[(size_t)NBATCH * HEADS * SEQ * HD];   // [b,h,l,d]
__device__ float g_K[(size_t)NBATCH * HEADS * SEQ * HD];
__device__ float g_V[(size_t)NBATCH * HEADS * SEQ * HD];
__device__ float g_O[(size_t)MROWS * EMBED];               // [b*l, e] pre-Wo

// ---------------- tf32 / mma / ldmatrix helpers ------------------------------
__device__ __forceinline__ unsigned f2tf(float f) {
    unsigned u;
    asm("cvt.rna.tf32.f32 %0, %1;" : "=r"(u) : "f"(f));
    return u;
}

__device__ __forceinline__ void mma8(float* c, unsigned a0, unsigned a1,
                                     unsigned a2, unsigned a3,
                                     unsigned b0, unsigned b1) {
    asm volatile(
        "mma.sync.aligned.m16n8k8.row.col.f32.tf32.tf32.f32 "
        "{%0,%1,%2,%3}, {%4,%5,%6,%7}, {%8,%9}, {%0,%1,%2,%3};"
        : "+f"(c[0]), "+f"(c[1]), "+f"(c[2]), "+f"(c[3])
        : "r"(a0), "r"(a1), "r"(a2), "r"(a3), "r"(b0), "r"(b1));
}

__device__ __forceinline__ void ldsm4(unsigned& r0, unsigned& r1, unsigned& r2,
                                      unsigned& r3, const unsigned* p) {
    unsigned addr = (unsigned)__cvta_generic_to_shared(p);
    asm volatile("ldmatrix.sync.aligned.m8n8.x4.shared.b16 {%0,%1,%2,%3}, [%4];"
                 : "=r"(r0), "=r"(r1), "=r"(r2), "=r"(r3) : "r"(addr));
}

// =============================================================================
// Projection GEMM: C(128x128) = A(128xK) * B(128xK)^T, tf32 mma.
// Double-buffered smem, ldmatrix fragment loads.
// smem rows = 16 data + 4 pad words: i*20 mod 32 distinct for 8 rows -> LDSM
// conflict-free. 8 warps 4x2; warp = 32 rows x 64 cols.
// =============================================================================
#define PSTR 20

__device__ __forceinline__ void gemm_mma_abt(const float* __restrict__ A,
                                             const float* __restrict__ B,
                                             float acc[2][8][4]) {
    __shared__ unsigned As[2][128 * PSTR];
    __shared__ unsigned Bs[2][128 * PSTR];

    const int tid = threadIdx.x, lane = tid & 31, wid = tid >> 5;
    const int wm = wid >> 1, wn = wid & 1;
    const int lr = tid >> 1, lk = (tid & 1) * 8;
    // ldmatrix lane->address offsets (A-style x4: 16 rows, two 4-col halves)
    const int aro = lane & 15, aco = (lane >> 4) * 4;
    // B-style x4: two 8-row n-tiles, two 4-col k-halves
    const int bro = (lane & 7) + ((lane >> 4) << 3), bco = ((lane >> 3) & 1) * 4;

    const float* Ap = A + (size_t)lr * EMBED + lk;
    const float* Bp = B + (size_t)lr * EMBED + lk;
    const int woff = lr * PSTR + lk;

    // prologue: stage 0
    {
        float4 a0 = *(const float4*)(Ap),     a1 = *(const float4*)(Ap + 4);
        float4 b0 = *(const float4*)(Bp),     b1 = *(const float4*)(Bp + 4);
        *(uint4*)&As[0][woff]     = make_uint4(f2tf(a0.x), f2tf(a0.y), f2tf(a0.z), f2tf(a0.w));
        *(uint4*)&As[0][woff + 4] = make_uint4(f2tf(a1.x), f2tf(a1.y), f2tf(a1.z), f2tf(a1.w));
        *(uint4*)&Bs[0][woff]     = make_uint4(f2tf(b0.x), f2tf(b0.y), f2tf(b0.z), f2tf(b0.w));
        *(uint4*)&Bs[0][woff + 4] = make_uint4(f2tf(b1.x), f2tf(b1.y), f2tf(b1.z), f2tf(b1.w));
    }
    __syncthreads();

    for (int k0 = 0; k0 < EMBED; k0 += 16) {
        const int cur = (k0 >> 4) & 1;
        const bool more = (k0 + 16) < EMBED;
        float4 na0, na1, nb0, nb1;
        if (more) {
            na0 = *(const float4*)(Ap + k0 + 16); na1 = *(const float4*)(Ap + k0 + 20);
            nb0 = *(const float4*)(Bp + k0 + 16); nb1 = *(const float4*)(Bp + k0 + 20);
        }

        const unsigned* pa = As[cur];
        const unsigned* pb = Bs[cur];
#pragma unroll
        for (int kk = 0; kk < 16; kk += 8) {
            unsigned af[2][4];
#pragma unroll
            for (int mt = 0; mt < 2; mt++)
                ldsm4(af[mt][0], af[mt][1], af[mt][2], af[mt][3],
                      pa + (wm * 32 + mt * 16 + aro) * PSTR + kk + aco);
            unsigned bf[8][2];
#pragma unroll
            for (int np = 0; np < 4; np++) {
                unsigned r0, r1, r2, r3;
                ldsm4(r0, r1, r2, r3,
                      pb + (wn * 64 + np * 16 + bro) * PSTR + kk + bco);
                bf[2 * np][0] = r0; bf[2 * np][1] = r1;
                bf[2 * np + 1][0] = r2; bf[2 * np + 1][1] = r3;
            }
#pragma unroll
            for (int mt = 0; mt < 2; mt++)
#pragma unroll
                for (int nt = 0; nt < 8; nt++)
                    mma8(acc[mt][nt], af[mt][0], af[mt][1], af[mt][2], af[mt][3],
                         bf[nt][0], bf[nt][1]);
        }

        if (more) {
            const int nxt = cur ^ 1;
            *(uint4*)&As[nxt][woff]     = make_uint4(f2tf(na0.x), f2tf(na0.y), f2tf(na0.z), f2tf(na0.w));
            *(uint4*)&As[nxt][woff + 4] = make_uint4(f2tf(na1.x), f2tf(na1.y), f2tf(na1.z), f2tf(na1.w));
            *(uint4*)&Bs[nxt][woff]     = make_uint4(f2tf(nb0.x), f2tf(nb0.y), f2tf(nb0.z), f2tf(nb0.w));
            *(uint4*)&Bs[nxt][woff + 4] = make_uint4(f2tf(nb1.x), f2tf(nb1.y), f2tf(nb1.z), f2tf(nb1.w));
        }
        __syncthreads();
    }
}

// QKV projection, scattered to head-major [b,h,l,d]
__global__ void __launch_bounds__(256) qkv_kernel(
    const float* __restrict__ q_in, const float* __restrict__ k_in,
    const float* __restrict__ v_in, const float* __restrict__ Wq,
    const float* __restrict__ Wk, const float* __restrict__ Wv) {
    const int z = blockIdx.z;
    const float* A = (z == 0) ? q_in : (z == 1) ? k_in : v_in;
    const float* W = (z == 0) ? Wq : (z == 1) ? Wk : Wv;
    float* dst = (z == 0) ? g_Q : (z == 1) ? g_K : g_V;

    A += (size_t)blockIdx.y * 128 * EMBED;
    W += (size_t)blockIdx.x * 128 * EMBED;

    float acc[2][8][4] = {};
    gemm_mma_abt(A, W, acc);

    const int lane = threadIdx.x & 31, wid = threadIdx.x >> 5;
    const int wm = wid >> 1, wn = wid & 1;
    const int g = lane >> 2, t4 = lane & 3;

#pragma unroll
    for (int mt = 0; mt < 2; mt++) {
#pragma unroll
        for (int rh = 0; rh < 2; rh++) {
            const int r = blockIdx.y * 128 + wm * 32 + mt * 16 + g + rh * 8;
            const int b = r >> 11, l = r & (SEQ - 1);
#pragma unroll
            for (int nt = 0; nt < 8; nt++) {
                const int c = blockIdx.x * 128 + wn * 64 + nt * 8 + t4 * 2;
                const int h = c >> 6, d = c & 63;
                float2 v = make_float2(acc[mt][nt][rh * 2], acc[mt][nt][rh * 2 + 1]);
                *(float2*)&dst[(((size_t)(b * HEADS + h)) * SEQ + l) * HD + d] = v;
            }
        }
    }
}

// Output projection: out = g_O @ Wo^T + bo
__global__ void __launch_bounds__(256) oproj_kernel(const float* __restrict__ Wo,
                                                    const float* __restrict__ bo,
                                                    float* __restrict__ out) {
    const float* A = g_O + (size_t)blockIdx.y * 128 * EMBED;
    const float* W = Wo  + (size_t)blockIdx.x * 128 * EMBED;

    float acc[2][8][4] = {};
    gemm_mma_abt(A, W, acc);

    const int lane = threadIdx.x & 31, wid = threadIdx.x >> 5;
    const int wm = wid >> 1, wn = wid & 1;
    const int g = lane >> 2, t4 = lane & 3;

#pragma unroll
    for (int mt = 0; mt < 2; mt++) {
#pragma unroll
        for (int rh = 0; rh < 2; rh++) {
            const int r = blockIdx.y * 128 + wm * 32 + mt * 16 + g + rh * 8;
#pragma unroll
            for (int nt = 0; nt < 8; nt++) {
                const int c = blockIdx.x * 128 + wn * 64 + nt * 8 + t4 * 2;
                float2 bb = *(const float2*)&bo[c];
                float2 v = make_float2(acc[mt][nt][rh * 2] + bb.x,
                                       acc[mt][nt][rh * 2 + 1] + bb.y);
                *(float2*)&out[(size_t)r * EMBED + c] = v;
            }
        }
    }
}

// =============================================================================
// Flash attention, tf32 mma + ldmatrix + in-warp softmax + in-register P.
// Q-tile 128, K-tile 64. Warp = 16 q-rows x 64 keys (8 warps).
// Smem: Q natural [128][68], K natural [64][68], V transposed [64][68].
// P (C-frag) -> PV A-frag via 8 shuffles per 16x8 tile (no smem round trip).
// =============================================================================
#define ASTR 68

__global__ void __launch_bounds__(256, 2) attn_kernel(const int* __restrict__ mask) {
    extern __shared__ unsigned smu[];
    unsigned* Qs = smu;               // [128][ASTR]
    unsigned* Ks = Qs + 128 * ASTR;   // [64][ASTR]
    unsigned* Vt = Ks + 64 * ASTR;    // [64][ASTR]  (Vt[d][key])

    const int qt = blockIdx.x, h = blockIdx.y, b = blockIdx.z;
    const int tid = threadIdx.x, lane = tid & 31, wid = tid >> 5;
    const int g = lane >> 2, t4 = lane & 3;
    const int aro = lane & 15, aco = (lane >> 4) * 4;
    const int bro = (lane & 7) + ((lane >> 4) << 3), bco = ((lane >> 3) & 1) * 4;

    const float* Qg = g_Q + ((size_t)(b * HEADS + h) * SEQ + qt * 128) * HD;
    const float* Kg = g_K + (size_t)(b * HEADS + h) * SEQ * HD;
    const float* Vg = g_V + (size_t)(b * HEADS + h) * SEQ * HD;
    const int*   mp = mask + (size_t)b * SEQ;

    // Q -> smem natural [row][d], tf32
    {
        const int qr = tid >> 1, qc = (tid & 1) * 32;
        const float* qp = Qg + (size_t)qr * HD + qc;
        unsigned* dq = Qs + qr * ASTR + qc;
#pragma unroll
        for (int j = 0; j < 8; j++) {
            float4 v = *(const float4*)(qp + j * 4);
            *(uint4*)(dq + j * 4) = make_uint4(f2tf(v.x), f2tf(v.y), f2tf(v.z), f2tf(v.w));
        }
    }

    float accO[8][4] = {};
    float m_i[2] = {-3.0e38f, -3.0e38f}, l_i[2] = {0.f, 0.f};

    // K prefetch: thread row kr = tid>>2, cols (tid&3)*16 + 16 floats
    const int kr = tid >> 2, kc = (tid & 3) * 16;
    float4 kreg[4];
    {
        const float* kp = Kg + (size_t)kr * HD + kc;
#pragma unroll
        for (int j = 0; j < 4; j++) kreg[j] = *(const float4*)(kp + j * 4);
    }
    // V mapping: thread row vr = tid&63, col base (tid>>6)*4, 4 float4 strided 16
    const int vr = tid & 63, vcb = (tid >> 6) * 4;

    for (int kt = 0; kt < SEQ / 64; kt++) {
        __syncthreads();   // sync1: previous PV done reading Ks/Vt
        // store K tile (natural [key][d])
        {
            unsigned* dk = Ks + kr * ASTR + kc;
#pragma unroll
            for (int j = 0; j < 4; j++)
                *(uint4*)(dk + j * 4) = make_uint4(f2tf(kreg[j].x), f2tf(kreg[j].y),
                                                   f2tf(kreg[j].z), f2tf(kreg[j].w));
        }
        // V loads for this tile (latency hidden behind S below)
        float4 vreg[4];
        {
            const float* vp = Vg + (size_t)(kt * 64 + vr) * HD + vcb;
#pragma unroll
            for (int j = 0; j < 4; j++) vreg[j] = *(const float4*)(vp + 16 * j);
        }
        __syncthreads();   // sync2: Ks (and Qs on iter 0) visible

        // ---- S = Q * K^T ----
        float s[8][4] = {};
#pragma unroll
        for (int k8 = 0; k8 < 64; k8 += 8) {
            unsigned aq0, aq1, aq2, aq3;
            ldsm4(aq0, aq1, aq2, aq3, Qs + (wid * 16 + aro) * ASTR + k8 + aco);
            unsigned bf[8][2];
#pragma unroll
            for (int np = 0; np < 4; np++) {
                unsigned r0, r1, r2, r3;
                ldsm4(r0, r1, r2, r3, Ks + (np * 16 + bro) * ASTR + k8 + bco);
                bf[2 * np][0] = r0; bf[2 * np][1] = r1;
                bf[2 * np + 1][0] = r2; bf[2 * np + 1][1] = r3;
            }
#pragma unroll
            for (int nt = 0; nt < 8; nt++)
                mma8(s[nt], aq0, aq1, aq2, aq3, bf[nt][0], bf[nt][1]);
        }

        // prefetch next K tile (latency hidden behind softmax + PV)
        if (kt + 1 < SEQ / 64) {
            const float* kp = Kg + (size_t)((kt + 1) * 64 + kr) * HD + kc;
#pragma unroll
            for (int j = 0; j < 4; j++) kreg[j] = *(const float4*)(kp + j * 4);
        }

        // ---- mask + scale ----
        const float scale = 0.125f;   // 1/sqrt(64)
#pragma unroll
        for (int nt = 0; nt < 8; nt++) {
            const int m0 = __ldg(&mp[kt * 64 + nt * 8 + t4 * 2]);
            const int m1 = __ldg(&mp[kt * 64 + nt * 8 + t4 * 2 + 1]);
#pragma unroll
            for (int c = 0; c < 4; c++)
                s[nt][c] = ((c & 1) ? m1 : m0) ? s[nt][c] * scale : -1.0e20f;
        }

        // ---- in-warp online softmax (rows g and g+8) ----
        float scf[2];
#pragma unroll
        for (int h2 = 0; h2 < 2; h2++) {
            float rm = -3.0e38f;
#pragma unroll
            for (int nt = 0; nt < 8; nt++)
                rm = fmaxf(rm, fmaxf(s[nt][h2 * 2], s[nt][h2 * 2 + 1]));
            rm = fmaxf(rm, __shfl_xor_sync(0xffffffffu, rm, 1));
            rm = fmaxf(rm, __shfl_xor_sync(0xffffffffu, rm, 2));
            const float mn = fmaxf(m_i[h2], rm);
            scf[h2] = __expf(m_i[h2] - mn);
            m_i[h2] = mn;
            float ps = 0.f;
#pragma unroll
            for (int nt = 0; nt < 8; nt++) {
                float e0 = __expf(s[nt][h2 * 2] - mn);
                float e1 = __expf(s[nt][h2 * 2 + 1] - mn);
                s[nt][h2 * 2] = e0; s[nt][h2 * 2 + 1] = e1;
                ps += e0 + e1;
            }
            ps += __shfl_xor_sync(0xffffffffu, ps, 1);
            ps += __shfl_xor_sync(0xffffffffu, ps, 2);
            l_i[h2] = l_i[h2] * scf[h2] + ps;
        }
        // rescale accumulators
#pragma unroll
        for (int nd = 0; nd < 8; nd++)
#pragma unroll
            for (int c = 0; c < 4; c++)
                accO[nd][c] *= scf[c >> 1];
        // convert P to tf32 in place (bits carried in float regs)
#pragma unroll
        for (int nt = 0; nt < 8; nt++)
#pragma unroll
            for (int c = 0; c < 4; c++)
                s[nt][c] = __uint_as_float(f2tf(s[nt][c]));

        // store V transposed: Vt[d][key]
        {
#pragma unroll
            for (int j = 0; j < 4; j++) {
                const int c0 = vcb + 16 * j;
                Vt[(c0 + 0) * ASTR + vr] = f2tf(vreg[j].x);
                Vt[(c0 + 1) * ASTR + vr] = f2tf(vreg[j].y);
                Vt[(c0 + 2) * ASTR + vr] = f2tf(vreg[j].z);
                Vt[(c0 + 3) * ASTR + vr] = f2tf(vreg[j].w);
            }
        }
        __syncthreads();   // sync3: Vt visible

        // ---- O += P * V (P A-frags built in-register via shuffles) ----
        const int src0 = (lane & ~3) + (t4 >> 1);
#pragma unroll
        for (int kk = 0; kk < 8; kk++) {
            float w00 = __shfl_sync(0xffffffffu, s[kk][0], src0);
            float w01 = __shfl_sync(0xffffffffu, s[kk][1], src0);
            float w02 = __shfl_sync(0xffffffffu, s[kk][2], src0);
            float w03 = __shfl_sync(0xffffffffu, s[kk][3], src0);
            float w10 = __shfl_sync(0xffffffffu, s[kk][0], src0 + 2);
            float w11 = __shfl_sync(0xffffffffu, s[kk][1], src0 + 2);
            float w12 = __shfl_sync(0xffffffffu, s[kk][2], src0 + 2);
            float w13 = __shfl_sync(0xffffffffu, s[kk][3], src0 + 2);
            const bool odd = (t4 & 1);
            unsigned a0 = __float_as_uint(odd ? w01 : w00);
            unsigned a1 = __float_as_uint(odd ? w03 : w02);
            unsigned a2 = __float_as_uint(odd ? w11 : w10);
            unsigned a3 = __float_as_uint(odd ? w13 : w12);

            unsigned bf[8][2];
#pragma unroll
            for (int np = 0; np < 4; np++) {
                unsigned r0, r1, r2, r3;
                ldsm4(r0, r1, r2, r3, Vt + (np * 16 + bro) * ASTR + kk * 8 + bco);
                bf[2 * np][0] = r0; bf[2 * np][1] = r1;
                bf[2 * np + 1][0] = r2; bf[2 * np + 1][1] = r3;
            }
#pragma unroll
            for (int nd = 0; nd < 8; nd++)
                mma8(accO[nd], a0, a1, a2, a3, bf[nd][0], bf[nd][1]);
        }
    }

    // ---- epilogue: normalize, write g_O [b*l, e] ----
#pragma unroll
    for (int h2 = 0; h2 < 2; h2++) {
        const float inv = 1.0f / l_i[h2];
        const int row = qt * 128 + wid * 16 + g + h2 * 8;
#pragma unroll
        for (int nd = 0; nd < 8; nd++) {
            const int d = nd * 8 + t4 * 2;
            float2 v = make_float2(accO[nd][h2 * 2] * inv, accO[nd][h2 * 2 + 1] * inv);
            *(float2*)&g_O[((size_t)b * SEQ + row) * EMBED + h * HD + d] = v;
        }
    }
}

// ---------------- launcher ---------------------------------------------------
extern "C" void kernel_launch(void* const* d_in, const int* in_sizes, int n_in,
                              void* d_out, int out_size) {
    const float* values = (const float*)d_in[0];
    const float* keys   = (const float*)d_in[1];
    const float* query  = (const float*)d_in[2];
    const int*   mask   = (const int*)d_in[3];
    const float* Wq     = (const float*)d_in[4];
    const float* Wk     = (const float*)d_in[5];
    const float* Wv     = (const float*)d_in[6];
    const float* Wo     = (const float*)d_in[7];
    const float* bo     = (const float*)d_in[8];
    float* out = (float*)d_out;

    const int attn_smem = (128 * ASTR + 64 * ASTR + 64 * ASTR) * (int)sizeof(unsigned); // 69632
    cudaFuncSetAttribute(attn_kernel, cudaFuncAttributeMaxDynamicSharedMemorySize,
                         attn_smem);

    dim3 gproj(EMBED / 128, MROWS / 128, 3);
    qkv_kernel<<<gproj, 256>>>(query, keys, values, Wq, Wk, Wv);

    dim3 gattn(SEQ / 128, HEADS, NBATCH);
    attn_kernel<<<gattn, 256, attn_smem>>>(mask);

    dim3 gout(EMBED / 128, MROWS / 128);
    oproj_kernel<<<gout, 256>>>(Wo, bo, out);
}

// round 17
// speedup vs baseline: 2.9786x; 1.0639x over previous
#include <cuda_runtime.h>
#include <cstdint>

#define EMBED 1024
#define HEADS 16
#define HD 64
#define NBATCH 2
#define SEQ 2048
#define MROWS (NBATCH * SEQ)   // 4096

// ---------------- scratch (allocation-free: __device__ globals) --------------
// g_Q/g_K/g_V/g_O hold tf32 bit patterns stored as float words.
__device__ float g_Q[(size_t)NBATCH * HEADS * SEQ * HD];   // [b,h,l,d]
__device__ float g_K[(size_t)NBATCH * HEADS * SEQ * HD];
__device__ float g_V[(size_t)NBATCH * HEADS * SEQ * HD];
__device__ float g_O[(size_t)MROWS * EMBED];               // [b*l, e] pre-Wo
__device__ float g_WTW[(size_t)4 * EMBED * EMBED];         // tf32(Wq,Wk,Wv,Wo)

// ---------------- helpers ----------------------------------------------------
__device__ __forceinline__ unsigned f2tf(float f) {
    unsigned u;
    asm("cvt.rna.tf32.f32 %0, %1;" : "=r"(u) : "f"(f));
    return u;
}

__device__ __forceinline__ void mma8(float* c, unsigned a0, unsigned a1,
                                     unsigned a2, unsigned a3,
                                     unsigned b0, unsigned b1) {
    asm volatile(
        "mma.sync.aligned.m16n8k8.row.col.f32.tf32.tf32.f32 "
        "{%0,%1,%2,%3}, {%4,%5,%6,%7}, {%8,%9}, {%0,%1,%2,%3};"
        : "+f"(c[0]), "+f"(c[1]), "+f"(c[2]), "+f"(c[3])
        : "r"(a0), "r"(a1), "r"(a2), "r"(a3), "r"(b0), "r"(b1));
}

__device__ __forceinline__ void ldsm4(unsigned& r0, unsigned& r1, unsigned& r2,
                                      unsigned& r3, const unsigned* p) {
    unsigned addr = (unsigned)__cvta_generic_to_shared(p);
    asm volatile("ldmatrix.sync.aligned.m8n8.x4.shared.b16 {%0,%1,%2,%3}, [%4];"
                 : "=r"(r0), "=r"(r1), "=r"(r2), "=r"(r3) : "r"(addr));
}

__device__ __forceinline__ void cpa16(unsigned saddr, const float* g) {
    asm volatile("cp.async.ca.shared.global [%0], [%1], 16;"
                 :: "r"(saddr), "l"(g) : "memory");
}
#define CP_COMMIT() asm volatile("cp.async.commit_group;" ::: "memory")
#define CP_WAIT(n)  asm volatile("cp.async.wait_group %0;" :: "n"(n) : "memory")

// ---------------- weight pre-convert (fp32 -> tf32 bits, 16 MB) --------------
__global__ void __launch_bounds__(256) cvt_w_kernel(const float* __restrict__ wq,
                                                    const float* __restrict__ wk,
                                                    const float* __restrict__ wv,
                                                    const float* __restrict__ wo) {
    const int z = blockIdx.z;
    const float* s = (z == 0) ? wq : (z == 1) ? wk : (z == 2) ? wv : wo;
    float* d = g_WTW + (size_t)z * EMBED * EMBED;
    const int i = blockIdx.x * 256 + threadIdx.x;   // float4 index
    float4 x = ((const float4*)s)[i];
    uint4 u = make_uint4(f2tf(x.x), f2tf(x.y), f2tf(x.z), f2tf(x.w));
    ((uint4*)d)[i] = u;
}

// =============================================================================
// Projection GEMM tiling: C(128x128) = A(128xK) * B(128xK)^T, K-chunk 32.
// 256 threads, 8 warps (4m x 2n): warp 32 rows x 64 cols.
// PSTR=36 words (==4 mod 32 -> conflict-free LDSM). Double-buffered.
// =============================================================================
#define PBK 32
#define PSTR 36
#define PA_WORDS (128 * PSTR)                // 4608
#define PSTAGE (2 * PA_WORDS)                // A + B per stage
#define PROJ_SMEM (2 * PSTAGE * 4)           // 73728 B

// compute one K-chunk from buffers pa (A) / pb (B)
__device__ __forceinline__ void proj_compute(const unsigned* pa, const unsigned* pb,
                                             float acc[2][8][4]) {
    const int lane = threadIdx.x & 31, wid = threadIdx.x >> 5;
    const int wm = wid >> 1, wn = wid & 1;
    const int aro = lane & 15, aco = (lane >> 4) * 4;
    const int bro = (lane & 7) + ((lane >> 4) << 3), bco = ((lane >> 3) & 1) * 4;
#pragma unroll
    for (int kk = 0; kk < PBK; kk += 8) {
        unsigned af[2][4];
#pragma unroll
        for (int mt = 0; mt < 2; mt++)
            ldsm4(af[mt][0], af[mt][1], af[mt][2], af[mt][3],
                  pa + (wm * 32 + mt * 16 + aro) * PSTR + kk + aco);
        unsigned bf[8][2];
#pragma unroll
        for (int np = 0; np < 4; np++) {
            unsigned r0, r1, r2, r3;
            ldsm4(r0, r1, r2, r3, pb + (wn * 64 + np * 16 + bro) * PSTR + kk + bco);
            bf[2 * np][0] = r0; bf[2 * np][1] = r1;
            bf[2 * np + 1][0] = r2; bf[2 * np + 1][1] = r3;
        }
#pragma unroll
        for (int mt = 0; mt < 2; mt++)
#pragma unroll
            for (int nt = 0; nt < 8; nt++)
                mma8(acc[mt][nt], af[mt][0], af[mt][1], af[mt][2], af[mt][3],
                     bf[nt][0], bf[nt][1]);
    }
}

// ---- qkv mainloop: A raw fp32 (LDG+cvt+STS), B tf32 bits via cp.async -------
__device__ __forceinline__ void gemm_mixed(const float* __restrict__ A,
                                           const float* __restrict__ B,
                                           float acc[2][8][4]) {
    extern __shared__ unsigned psm[];
    unsigned sbyte = (unsigned)__cvta_generic_to_shared(psm);
    const int tid = threadIdx.x;
    const int row = tid >> 1, half = (tid & 1) * 16;   // 16 words per thread

    const float* Ap = A + (size_t)row * EMBED + half;
    const float* Bp = B + (size_t)row * EMBED + half;
    const unsigned soff = (unsigned)((row * PSTR + half) * 4);

    // prologue: A(0) regs + STS, B(0) cp.async
    float4 ar[4];
#pragma unroll
    for (int j = 0; j < 4; j++) ar[j] = *(const float4*)(Ap + j * 4);
#pragma unroll
    for (int j = 0; j < 4; j++)
        cpa16(sbyte + PA_WORDS * 4 + soff + j * 16, Bp + j * 4);
    CP_COMMIT();
#pragma unroll
    for (int j = 0; j < 4; j++)
        *(uint4*)((char*)psm + soff + j * 16) =
            make_uint4(f2tf(ar[j].x), f2tf(ar[j].y), f2tf(ar[j].z), f2tf(ar[j].w));

    for (int kt = 0; kt < EMBED / PBK; kt++) {
        const bool more = (kt + 1) < EMBED / PBK;
        float4 ar2[4];
        if (more) {
            const unsigned nb = ((kt + 1) & 1) * PSTAGE * 4;
#pragma unroll
            for (int j = 0; j < 4; j++) ar2[j] = *(const float4*)(Ap + (kt + 1) * PBK + j * 4);
#pragma unroll
            for (int j = 0; j < 4; j++)
                cpa16(sbyte + nb + PA_WORDS * 4 + soff + j * 16, Bp + (kt + 1) * PBK + j * 4);
            CP_COMMIT();
            CP_WAIT(1);
        } else {
            CP_WAIT(0);
        }
        __syncthreads();                       // A(kt)/B(kt) visible to all warps
        const unsigned* pa = psm + (kt & 1) * PSTAGE;
        proj_compute(pa, pa + PA_WORDS, acc);
        if (more) {
            char* nb = (char*)psm + ((kt + 1) & 1) * PSTAGE * 4;
#pragma unroll
            for (int j = 0; j < 4; j++)
                *(uint4*)(nb + soff + j * 16) = make_uint4(f2tf(ar2[j].x), f2tf(ar2[j].y),
                                                           f2tf(ar2[j].z), f2tf(ar2[j].w));
        }
        __syncthreads();                       // compute(kt) + STS(kt+1) done everywhere
    }
}

// ---- oproj mainloop: both operands tf32 bits via cp.async -------------------
__device__ __forceinline__ void gemm_async(const float* __restrict__ A,
                                           const float* __restrict__ B,
                                           float acc[2][8][4]) {
    extern __shared__ unsigned psm[];
    unsigned sbyte = (unsigned)__cvta_generic_to_shared(psm);
    const int tid = threadIdx.x;
    const int row = tid >> 1, half = (tid & 1) * 16;

    const float* Ap = A + (size_t)row * EMBED + half;
    const float* Bp = B + (size_t)row * EMBED + half;
    const unsigned soff = (unsigned)((row * PSTR + half) * 4);

#pragma unroll
    for (int j = 0; j < 4; j++) {
        cpa16(sbyte + soff + j * 16, Ap + j * 4);
        cpa16(sbyte + PA_WORDS * 4 + soff + j * 16, Bp + j * 4);
    }
    CP_COMMIT();
    for (int kt = 0; kt < EMBED / PBK; kt++) {
        const bool more = (kt + 1) < EMBED / PBK;
        if (more) {
            const unsigned nb = ((kt + 1) & 1) * PSTAGE * 4;
#pragma unroll
            for (int j = 0; j < 4; j++) {
                cpa16(sbyte + nb + soff + j * 16, Ap + (kt + 1) * PBK + j * 4);
                cpa16(sbyte + nb + PA_WORDS * 4 + soff + j * 16, Bp + (kt + 1) * PBK + j * 4);
            }
            CP_COMMIT();
            CP_WAIT(1);
        } else {
            CP_WAIT(0);
        }
        __syncthreads();
        const unsigned* pa = psm + (kt & 1) * PSTAGE;
        proj_compute(pa, pa + PA_WORDS, acc);
        __syncthreads();
    }
}

// QKV projection -> head-major [b,h,l,d], stored as tf32 bits
__global__ void __launch_bounds__(256, 1) qkv_kernel(
    const float* __restrict__ q_in, const float* __restrict__ k_in,
    const float* __restrict__ v_in) {
    const int z = blockIdx.z;
    const float* A = ((z == 0) ? q_in : (z == 1) ? k_in : v_in)
                     + (size_t)blockIdx.y * 128 * EMBED;
    const float* B = g_WTW + (size_t)z * EMBED * EMBED + (size_t)blockIdx.x * 128 * EMBED;
    float* dst = (z == 0) ? g_Q : (z == 1) ? g_K : g_V;

    float acc[2][8][4] = {};
    gemm_mixed(A, B, acc);

    const int lane = threadIdx.x & 31, wid = threadIdx.x >> 5;
    const int wm = wid >> 1, wn = wid & 1;
    const int g = lane >> 2, t4 = lane & 3;
#pragma unroll
    for (int mt = 0; mt < 2; mt++) {
#pragma unroll
        for (int rh = 0; rh < 2; rh++) {
            const int r = blockIdx.y * 128 + wm * 32 + mt * 16 + g + rh * 8;
            const int b = r >> 11, l = r & (SEQ - 1);
#pragma unroll
            for (int nt = 0; nt < 8; nt++) {
                const int c = blockIdx.x * 128 + wn * 64 + nt * 8 + t4 * 2;
                const int h = c >> 6, d = c & 63;
                float2 v = make_float2(__uint_as_float(f2tf(acc[mt][nt][rh * 2])),
                                       __uint_as_float(f2tf(acc[mt][nt][rh * 2 + 1])));
                *(float2*)&dst[(((size_t)(b * HEADS + h)) * SEQ + l) * HD + d] = v;
            }
        }
    }
}

// Output projection: out = g_O @ Wo^T + bo  (fp32 output)
__global__ void __launch_bounds__(256, 1) oproj_kernel(const float* __restrict__ bo,
                                                       float* __restrict__ out) {
    const float* A = g_O + (size_t)blockIdx.y * 128 * EMBED;
    const float* B = g_WTW + (size_t)3 * EMBED * EMBED + (size_t)blockIdx.x * 128 * EMBED;

    float acc[2][8][4] = {};
    gemm_async(A, B, acc);

    const int lane = threadIdx.x & 31, wid = threadIdx.x >> 5;
    const int wm = wid >> 1, wn = wid & 1;
    const int g = lane >> 2, t4 = lane & 3;
#pragma unroll
    for (int mt = 0; mt < 2; mt++) {
#pragma unroll
        for (int rh = 0; rh < 2; rh++) {
            const int r = blockIdx.y * 128 + wm * 32 + mt * 16 + g + rh * 8;
#pragma unroll
            for (int nt = 0; nt < 8; nt++) {
                const int c = blockIdx.x * 128 + wn * 64 + nt * 8 + t4 * 2;
                float2 bb = *(const float2*)&bo[c];
                float2 v = make_float2(acc[mt][nt][rh * 2] + bb.x,
                                       acc[mt][nt][rh * 2 + 1] + bb.y);
                *(float2*)&out[(size_t)r * EMBED + c] = v;
            }
        }
    }
}

// =============================================================================
// Flash attention: 128 threads, 4 warps, warp = 32 q-rows x 64 keys.
// Q/K/V already tf32 bits -> raw cp.async staging, K/V double-buffered.
// V kept NATURAL [key][d]; PV B-fragments via scalar LDS.
// P built in-register via shuffles.
// =============================================================================
#define ASTR 68
#define QW (128 * ASTR)          // 8704 words
#define KW (64 * ASTR)           // 4352 words
#define ATTN_SMEM ((QW + 4 * KW) * 4)   // 104448 B

__global__ void __launch_bounds__(128) attn_kernel(const int* __restrict__ mask) {
    extern __shared__ unsigned smu[];
    unsigned sbyte = (unsigned)__cvta_generic_to_shared(smu);

    const int qt = blockIdx.x, h = blockIdx.y, b = blockIdx.z;
    const int tid = threadIdx.x, lane = tid & 31, wid = tid >> 5;
    const int g = lane >> 2, t4 = lane & 3;
    const int aro = lane & 15, aco = (lane >> 4) * 4;
    const int bro = (lane & 7) + ((lane >> 4) << 3), bco = ((lane >> 3) & 1) * 4;

    const float* Qg = g_Q + ((size_t)(b * HEADS + h) * SEQ + qt * 128) * HD;
    const float* Kg = g_K + (size_t)(b * HEADS + h) * SEQ * HD;
    const float* Vg = g_V + (size_t)(b * HEADS + h) * SEQ * HD;
    const int*   mp = mask + (size_t)b * SEQ;

    const int sr = tid >> 3, sc = (tid & 7) * 8;   // staging row/col (words)

    // prologue: Q tile + K0/V0 as one cp.async group
    {
#pragma unroll
        for (int p = 0; p < 8; p++) {
            const int row = sr + 16 * p;
            unsigned d = sbyte + (unsigned)((row * ASTR + sc) * 4);
            const float* s = Qg + (size_t)row * HD + sc;
            cpa16(d, s); cpa16(d + 16, s + 4);
        }
#pragma unroll
        for (int p = 0; p < 4; p++) {
            const int row = sr + 16 * p;
            unsigned off = (unsigned)((row * ASTR + sc) * 4);
            const float* ks = Kg + (size_t)row * HD + sc;
            cpa16(sbyte + QW * 4 + off, ks);
            cpa16(sbyte + QW * 4 + off + 16, ks + 4);
            const float* vs = Vg + (size_t)row * HD + sc;
            cpa16(sbyte + (QW + 2 * KW) * 4 + off, vs);
            cpa16(sbyte + (QW + 2 * KW) * 4 + off + 16, vs + 4);
        }
        CP_COMMIT();
    }

    float accO[2][8][4] = {};
    float m_i[2][2] = {{-3.0e38f, -3.0e38f}, {-3.0e38f, -3.0e38f}};
    float l_i[2][2] = {};

    for (int kt = 0; kt < SEQ / 64; kt++) {
        if (kt + 1 < SEQ / 64) {
            const int st = (kt + 1) & 1;
#pragma unroll
            for (int p = 0; p < 4; p++) {
                const int row = sr + 16 * p;
                unsigned off = (unsigned)((row * ASTR + sc) * 4);
                const float* ks = Kg + (size_t)((kt + 1) * 64 + row) * HD + sc;
                cpa16(sbyte + (QW + st * KW) * 4 + off, ks);
                cpa16(sbyte + (QW + st * KW) * 4 + off + 16, ks + 4);
                const float* vs = Vg + (size_t)((kt + 1) * 64 + row) * HD + sc;
                cpa16(sbyte + (QW + (2 + st) * KW) * 4 + off, vs);
                cpa16(sbyte + (QW + (2 + st) * KW) * 4 + off + 16, vs + 4);
            }
            CP_COMMIT();
            CP_WAIT(1);
        } else {
            CP_WAIT(0);
        }
        __syncthreads();
        const unsigned* Ks = smu + QW + (kt & 1) * KW;
        const unsigned* Vs = smu + QW + (2 + (kt & 1)) * KW;

        // ---- S = Q * K^T  (per warp: 32 q-rows x 64 keys) ----
        float s[2][8][4] = {};
#pragma unroll
        for (int k8 = 0; k8 < 64; k8 += 8) {
            unsigned af[2][4];
#pragma unroll
            for (int mt = 0; mt < 2; mt++)
                ldsm4(af[mt][0], af[mt][1], af[mt][2], af[mt][3],
                      smu + (wid * 32 + mt * 16 + aro) * ASTR + k8 + aco);
            unsigned bf[8][2];
#pragma unroll
            for (int np = 0; np < 4; np++) {
                unsigned r0, r1, r2, r3;
                ldsm4(r0, r1, r2, r3, Ks + (np * 16 + bro) * ASTR + k8 + bco);
                bf[2 * np][0] = r0; bf[2 * np][1] = r1;
                bf[2 * np + 1][0] = r2; bf[2 * np + 1][1] = r3;
            }
#pragma unroll
            for (int mt = 0; mt < 2; mt++)
#pragma unroll
                for (int nt = 0; nt < 8; nt++)
                    mma8(s[mt][nt], af[mt][0], af[mt][1], af[mt][2], af[mt][3],
                         bf[nt][0], bf[nt][1]);
        }

        // ---- mask + scale ----
        const float scale = 0.125f;   // 1/sqrt(64)
#pragma unroll
        for (int nt = 0; nt < 8; nt++) {
            const int m0 = __ldg(&mp[kt * 64 + nt * 8 + t4 * 2]);
            const int m1 = __ldg(&mp[kt * 64 + nt * 8 + t4 * 2 + 1]);
#pragma unroll
            for (int mt = 0; mt < 2; mt++)
#pragma unroll
                for (int c = 0; c < 4; c++)
                    s[mt][nt][c] = ((c & 1) ? m1 : m0) ? s[mt][nt][c] * scale : -1.0e20f;
        }

        // ---- in-warp online softmax (4 row-states: mt x h2) ----
        float scf[2][2];
#pragma unroll
        for (int mt = 0; mt < 2; mt++) {
#pragma unroll
            for (int h2 = 0; h2 < 2; h2++) {
                float rm = -3.0e38f;
#pragma unroll
                for (int nt = 0; nt < 8; nt++)
                    rm = fmaxf(rm, fmaxf(s[mt][nt][h2 * 2], s[mt][nt][h2 * 2 + 1]));
                rm = fmaxf(rm, __shfl_xor_sync(0xffffffffu, rm, 1));
                rm = fmaxf(rm, __shfl_xor_sync(0xffffffffu, rm, 2));
                const float mn = fmaxf(m_i[mt][h2], rm);
                scf[mt][h2] = __expf(m_i[mt][h2] - mn);
                m_i[mt][h2] = mn;
                float ps = 0.f;
#pragma unroll
                for (int nt = 0; nt < 8; nt++) {
                    float e0 = __expf(s[mt][nt][h2 * 2] - mn);
                    float e1 = __expf(s[mt][nt][h2 * 2 + 1] - mn);
                    s[mt][nt][h2 * 2] = e0; s[mt][nt][h2 * 2 + 1] = e1;
                    ps += e0 + e1;
                }
                ps += __shfl_xor_sync(0xffffffffu, ps, 1);
                ps += __shfl_xor_sync(0xffffffffu, ps, 2);
                l_i[mt][h2] = l_i[mt][h2] * scf[mt][h2] + ps;
            }
        }
#pragma unroll
        for (int mt = 0; mt < 2; mt++)
#pragma unroll
            for (int nd = 0; nd < 8; nd++)
#pragma unroll
                for (int c = 0; c < 4; c++)
                    accO[mt][nd][c] *= scf[mt][c >> 1];
        // convert P to tf32 bits in place
#pragma unroll
        for (int mt = 0; mt < 2; mt++)
#pragma unroll
            for (int nt = 0; nt < 8; nt++)
#pragma unroll
                for (int c = 0; c < 4; c++)
                    s[mt][nt][c] = __uint_as_float(f2tf(s[mt][nt][c]));

        // ---- O += P * V (A via shuffles; B via scalar LDS) ----
        const int src0 = (lane & ~3) + (t4 >> 1);
        const bool odd = (t4 & 1);
#pragma unroll
        for (int kk = 0; kk < 8; kk++) {
            unsigned bfv[8][2];
#pragma unroll
            for (int nd = 0; nd < 8; nd++) {
                bfv[nd][0] = Vs[(kk * 8 + t4) * ASTR + nd * 8 + g];
                bfv[nd][1] = Vs[(kk * 8 + t4 + 4) * ASTR + nd * 8 + g];
            }
#pragma unroll
            for (int mt = 0; mt < 2; mt++) {
                float w00 = __shfl_sync(0xffffffffu, s[mt][kk][0], src0);
                float w01 = __shfl_sync(0xffffffffu, s[mt][kk][1], src0);
                float w02 = __shfl_sync(0xffffffffu, s[mt][kk][2], src0);
                float w03 = __shfl_sync(0xffffffffu, s[mt][kk][3], src0);
                float w10 = __shfl_sync(0xffffffffu, s[mt][kk][0], src0 + 2);
                float w11 = __shfl_sync(0xffffffffu, s[mt][kk][1], src0 + 2);
                float w12 = __shfl_sync(0xffffffffu, s[mt][kk][2], src0 + 2);
                float w13 = __shfl_sync(0xffffffffu, s[mt][kk][3], src0 + 2);
                unsigned a0 = __float_as_uint(odd ? w01 : w00);
                unsigned a1 = __float_as_uint(odd ? w03 : w02);
                unsigned a2 = __float_as_uint(odd ? w11 : w10);
                unsigned a3 = __float_as_uint(odd ? w13 : w12);
#pragma unroll
                for (int nd = 0; nd < 8; nd++)
                    mma8(accO[mt][nd], a0, a1, a2, a3, bfv[nd][0], bfv[nd][1]);
            }
        }
        __syncthreads();   // PV done with this K/V buffer before next issue
    }

    // ---- epilogue: normalize, write g_O as tf32 bits ----
#pragma unroll
    for (int mt = 0; mt < 2; mt++) {
#pragma unroll
        for (int h2 = 0; h2 < 2; h2++) {
            const float inv = 1.0f / l_i[mt][h2];
            const int row = qt * 128 + wid * 32 + mt * 16 + g + h2 * 8;
#pragma unroll
            for (int nd = 0; nd < 8; nd++) {
                const int d = nd * 8 + t4 * 2;
                float2 v = make_float2(
                    __uint_as_float(f2tf(accO[mt][nd][h2 * 2] * inv)),
                    __uint_as_float(f2tf(accO[mt][nd][h2 * 2 + 1] * inv)));
                *(float2*)&g_O[((size_t)b * SEQ + row) * EMBED + h * HD + d] = v;
            }
        }
    }
}

// ---------------- launcher ---------------------------------------------------
extern "C" void kernel_launch(void* const* d_in, const int* in_sizes, int n_in,
                              void* d_out, int out_size) {
    const float* values = (const float*)d_in[0];
    const float* keys   = (const float*)d_in[1];
    const float* query  = (const float*)d_in[2];
    const int*   mask   = (const int*)d_in[3];
    const float* Wq     = (const float*)d_in[4];
    const float* Wk     = (const float*)d_in[5];
    const float* Wv     = (const float*)d_in[6];
    const float* Wo     = (const float*)d_in[7];
    const float* bo     = (const float*)d_in[8];
    float* out = (float*)d_out;

    cudaFuncSetAttribute(qkv_kernel, cudaFuncAttributeMaxDynamicSharedMemorySize, PROJ_SMEM);
    cudaFuncSetAttribute(oproj_kernel, cudaFuncAttributeMaxDynamicSharedMemorySize, PROJ_SMEM);
    cudaFuncSetAttribute(attn_kernel, cudaFuncAttributeMaxDynamicSharedMemorySize, ATTN_SMEM);

    // pre-convert weights to tf32 bits (16 MB scratch)
    cvt_w_kernel<<<dim3(EMBED * EMBED / 4 / 256, 1, 4), 256>>>(Wq, Wk, Wv, Wo);

    // QKV projections
    qkv_kernel<<<dim3(EMBED / 128, MROWS / 128, 3), 256, PROJ_SMEM>>>(query, keys, values);

    // flash attention
    attn_kernel<<<dim3(SEQ / 128, HEADS, NBATCH), 128, ATTN_SMEM>>>(mask);

    // output projection
    oproj_kernel<<<dim3(EMBED / 128, MROWS / 128), 256, PROJ_SMEM>>>(bo, out);
}